// round 12
// baseline (speedup 1.0000x reference)
#include <cuda_runtime.h>
#include <math.h>

#define NMAX 100000
#define EMAX 3200000
#define F_IN 128
#define HID  16
#define NC   10
#define CP   12   // layer-2 row stride: 12 floats = 48B, float4-aligned

// ---- scratch (static device globals; no allocation allowed) ----
__device__ float g_g1  [NMAX * HID];  // (x@W1) * dinv[src-side]
__device__ float g_g2  [NMAX * CP];   // (h@W2) * dinv, padded to 12
__device__ float g_dinv[NMAX];
__device__ int   g_cnt [NMAX];        // in-degree (dst counts)
__device__ int   g_cnt2[NMAX];        // placement cursors
__device__ int   g_base[NMAX];        // CSR row offsets (by dst)
__device__ int   g_bsum[512];         // block sums for scan
__device__ int   g_csr [EMAX];        // src indices grouped by dst

// ---------------------------------------------------------------
__global__ void zero_kernel(int n) {
    int i = blockIdx.x * blockDim.x + threadIdx.x;
    if (i < n) { g_cnt[i] = 0; g_cnt2[i] = 0; }
}

__global__ void deg_kernel(const int* __restrict__ dst, int e) {
    int i = blockIdx.x * blockDim.x + threadIdx.x;
    if (i < e) atomicAdd(&g_cnt[dst[i]], 1);
}

// ---- scan stage 1 (+ fused dinv): per-block sums of g_cnt ----
__global__ __launch_bounds__(256) void scan1_kernel(int n) {
    __shared__ int wsum[8];
    int i = blockIdx.x * 256 + threadIdx.x;
    int lane = threadIdx.x & 31, warp = threadIdx.x >> 5;
    int v = (i < n) ? g_cnt[i] : 0;
    if (i < n) g_dinv[i] = rsqrtf((float)v + 1.0f);
    int s = v;
#pragma unroll
    for (int d = 16; d > 0; d >>= 1) s += __shfl_down_sync(~0u, s, d);
    if (lane == 0) wsum[warp] = s;
    __syncthreads();
    if (threadIdx.x == 0) {
        int t = 0;
#pragma unroll
        for (int w = 0; w < 8; ++w) t += wsum[w];
        g_bsum[blockIdx.x] = t;
    }
}

// ---- scan stage 2+3 fused -> g_base ----
__global__ __launch_bounds__(256) void scan3_kernel(int n) {
    __shared__ int wsum[8];
    __shared__ int wred[8];
    __shared__ int s_boff;
    int lane = threadIdx.x & 31, warp = threadIdx.x >> 5;

    int partial = 0;
    for (int j = threadIdx.x; j < blockIdx.x; j += 256) partial += g_bsum[j];
#pragma unroll
    for (int d = 16; d > 0; d >>= 1) partial += __shfl_down_sync(~0u, partial, d);
    if (lane == 0) wred[warp] = partial;
    __syncthreads();
    if (threadIdx.x == 0) {
        int t = 0;
#pragma unroll
        for (int w = 0; w < 8; ++w) t += wred[w];
        s_boff = t;
    }

    int i = blockIdx.x * 256 + threadIdx.x;
    int orig = (i < n) ? g_cnt[i] : 0;
    int v = orig;
#pragma unroll
    for (int d = 1; d < 32; d <<= 1) {
        int t = __shfl_up_sync(~0u, v, d);
        if (lane >= d) v += t;
    }
    if (lane == 31) wsum[warp] = v;
    __syncthreads();
    if (warp == 0 && lane < 8) {
        int s = wsum[lane];
#pragma unroll
        for (int d = 1; d < 8; d <<= 1) {
            int t = __shfl_up_sync(0xffu, s, d);
            if (lane >= d) s += t;
        }
        wsum[lane] = s;
    }
    __syncthreads();
    int wbase = (warp > 0) ? wsum[warp - 1] : 0;
    if (i < n) g_base[i] = s_boff + wbase + v - orig;
}

// ---- CSR placement ----
__global__ void place_kernel(const int* __restrict__ src,
                             const int* __restrict__ dst, int e) {
    int i = blockIdx.x * blockDim.x + threadIdx.x;
    if (i >= e) return;
    int d = dst[i];
    int pos = g_base[d] + atomicAdd(&g_cnt2[d], 1);
    g_csr[pos] = src[i];
}

// ---- GEMM1: g1 = (x @ W1) * dinv (warp-staged; measured-good) ----
__global__ __launch_bounds__(256) void gemm1_kernel(const float* __restrict__ x,
                                                    const float* __restrict__ W1,
                                                    int n) {
    __shared__ float w1s[F_IN * HID];
    __shared__ float xs[8][32][33];
#pragma unroll
    for (int i = threadIdx.x; i < F_IN * HID; i += 256)
        w1s[i] = W1[i];
    __syncthreads();

    const int warp = threadIdx.x >> 5;
    const int lane = threadIdx.x & 31;
    const int row0 = blockIdx.x * 256 + warp * 32;
    const int myrow = row0 + lane;

    float acc[16];
#pragma unroll
    for (int o = 0; o < 16; ++o) acc[o] = 0.f;

#pragma unroll 1
    for (int kc = 0; kc < 4; ++kc) {
#pragma unroll 8
        for (int r = 0; r < 32; ++r) {
            int row = row0 + r;
            xs[warp][r][lane] = (row < n)
                ? x[(size_t)row * F_IN + kc * 32 + lane] : 0.f;
        }
        __syncwarp();
#pragma unroll
        for (int k = 0; k < 32; ++k) {
            float xv = xs[warp][lane][k];
            const float* w = w1s + (kc * 32 + k) * HID;
            float4 wa = *(const float4*)(w + 0);
            float4 wb = *(const float4*)(w + 4);
            float4 wc = *(const float4*)(w + 8);
            float4 wd = *(const float4*)(w + 12);
            acc[0]  = fmaf(xv, wa.x, acc[0]);  acc[1]  = fmaf(xv, wa.y, acc[1]);
            acc[2]  = fmaf(xv, wa.z, acc[2]);  acc[3]  = fmaf(xv, wa.w, acc[3]);
            acc[4]  = fmaf(xv, wb.x, acc[4]);  acc[5]  = fmaf(xv, wb.y, acc[5]);
            acc[6]  = fmaf(xv, wb.z, acc[6]);  acc[7]  = fmaf(xv, wb.w, acc[7]);
            acc[8]  = fmaf(xv, wc.x, acc[8]);  acc[9]  = fmaf(xv, wc.y, acc[9]);
            acc[10] = fmaf(xv, wc.z, acc[10]); acc[11] = fmaf(xv, wc.w, acc[11]);
            acc[12] = fmaf(xv, wd.x, acc[12]); acc[13] = fmaf(xv, wd.y, acc[13]);
            acc[14] = fmaf(xv, wd.z, acc[14]); acc[15] = fmaf(xv, wd.w, acc[15]);
        }
        __syncwarp();
    }

    if (myrow < n) {
        float dv = g_dinv[myrow];
        float* out = g_g1 + (size_t)myrow * HID;
#pragma unroll
        for (int o = 0; o < 16; o += 4)
            *(float4*)(out + o) = make_float4(acc[o] * dv, acc[o + 1] * dv,
                                              acc[o + 2] * dv, acc[o + 3] * dv);
    }
}

// ---- gf1: fused gather(layer1) + relu + GEMM2 epilogue.
// Warp per node: gather 16-wide sums of g_g1[src]; butterfly; lanes 0-3
// compute h quarters, partial h@W2, reduce over lanes 0-3, lane 0 writes
// the 12-wide g2 row (incl. *dv and zero pads). ----
__global__ __launch_bounds__(256) void gf1_kernel(const float* __restrict__ b1,
                                                  const float* __restrict__ W2,
                                                  int n) {
    __shared__ float w2s[HID * NC];
    __shared__ float b1s[HID];
    int tid = threadIdx.x;
    if (tid < HID * NC) w2s[tid] = W2[tid];
    if (tid < HID)      b1s[tid] = b1[tid];
    __syncthreads();

    int gw = (blockIdx.x * 256 + tid) >> 5;
    if (gw >= n) return;
    int lane = tid & 31;
    int eq = lane >> 2, q = lane & 3;
    int m = g_cnt[gw];
    const int* cs = g_csr + g_base[gw];

    float4 acc = make_float4(0.f, 0.f, 0.f, 0.f);
    int j = eq;
    for (; j + 8 < m; j += 16) {
        int s0 = cs[j], s1 = cs[j + 8];
        float4 a = *(const float4*)(g_g1 + (size_t)s0 * HID + q * 4);
        float4 b = *(const float4*)(g_g1 + (size_t)s1 * HID + q * 4);
        acc.x += a.x + b.x; acc.y += a.y + b.y;
        acc.z += a.z + b.z; acc.w += a.w + b.w;
    }
    for (; j < m; j += 8) {
        int s = cs[j];
        float4 a = *(const float4*)(g_g1 + (size_t)s * HID + q * 4);
        acc.x += a.x; acc.y += a.y; acc.z += a.z; acc.w += a.w;
    }
#pragma unroll
    for (int st = 4; st < 32; st <<= 1) {
        acc.x += __shfl_xor_sync(~0u, acc.x, st);
        acc.y += __shfl_xor_sync(~0u, acc.y, st);
        acc.z += __shfl_xor_sync(~0u, acc.z, st);
        acc.w += __shfl_xor_sync(~0u, acc.w, st);
    }

    if (lane < 4) {
        float dv = g_dinv[gw];
        float4 g = *(const float4*)(g_g1 + (size_t)gw * HID + q * 4);
        float h[4];
        h[0] = fmaxf(fmaf(dv, acc.x + g.x, b1s[q * 4 + 0]), 0.f);
        h[1] = fmaxf(fmaf(dv, acc.y + g.y, b1s[q * 4 + 1]), 0.f);
        h[2] = fmaxf(fmaf(dv, acc.z + g.z, b1s[q * 4 + 2]), 0.f);
        h[3] = fmaxf(fmaf(dv, acc.w + g.w, b1s[q * 4 + 3]), 0.f);

        float p[NC];
#pragma unroll
        for (int c = 0; c < NC; ++c) p[c] = 0.f;
#pragma unroll
        for (int jj = 0; jj < 4; ++jj) {
            const float* w = w2s + (q * 4 + jj) * NC;
            float hv = h[jj];
#pragma unroll
            for (int c = 0; c < NC; ++c) p[c] = fmaf(hv, w[c], p[c]);
        }
#pragma unroll
        for (int st = 1; st < 4; st <<= 1) {
#pragma unroll
            for (int c = 0; c < NC; ++c)
                p[c] += __shfl_xor_sync(0xF, p[c], st);
        }
        if (lane == 0) {
            float* o = g_g2 + (size_t)gw * CP;
            ((float4*)o)[0] = make_float4(p[0] * dv, p[1] * dv, p[2] * dv, p[3] * dv);
            ((float4*)o)[1] = make_float4(p[4] * dv, p[5] * dv, p[6] * dv, p[7] * dv);
            ((float4*)o)[2] = make_float4(p[8] * dv, p[9] * dv, 0.f, 0.f);
        }
    }
}

// ---- gf2: fused gather(layer2) + bias + softmax -> d_out.
// Warp per node: gather 12-wide sums of g_g2[src]; butterfly; lanes 0-2
// hold logit quarters (lane2 z,w and all of lane3 neutral), softmax via
// shuffles over lanes 0-3, lanes 0-2 write out[v*10 + q*4]. ----
__global__ __launch_bounds__(256) void gf2_kernel(const float* __restrict__ b2,
                                                  float* __restrict__ outp,
                                                  int n) {
    __shared__ float b2s[HID];
    if (threadIdx.x < HID)
        b2s[threadIdx.x] = (threadIdx.x < NC) ? b2[threadIdx.x] : 0.f;
    __syncthreads();

    int gw = (blockIdx.x * 256 + threadIdx.x) >> 5;
    if (gw >= n) return;
    int lane = threadIdx.x & 31;
    int eq = lane >> 2, q = lane & 3;
    int m = g_cnt[gw];
    const int* cs = g_csr + g_base[gw];

    float4 acc = make_float4(0.f, 0.f, 0.f, 0.f);
    if (q < 3) {
        int j = eq;
        for (; j + 8 < m; j += 16) {
            int s0 = cs[j], s1 = cs[j + 8];
            float4 a = *(const float4*)(g_g2 + (size_t)s0 * CP + q * 4);
            float4 b = *(const float4*)(g_g2 + (size_t)s1 * CP + q * 4);
            acc.x += a.x + b.x; acc.y += a.y + b.y;
            acc.z += a.z + b.z; acc.w += a.w + b.w;
        }
        for (; j < m; j += 8) {
            int s = cs[j];
            float4 a = *(const float4*)(g_g2 + (size_t)s * CP + q * 4);
            acc.x += a.x; acc.y += a.y; acc.z += a.z; acc.w += a.w;
        }
    }
#pragma unroll
    for (int st = 4; st < 32; st <<= 1) {
        acc.x += __shfl_xor_sync(~0u, acc.x, st);
        acc.y += __shfl_xor_sync(~0u, acc.y, st);
        acc.z += __shfl_xor_sync(~0u, acc.z, st);
        acc.w += __shfl_xor_sync(~0u, acc.w, st);
    }

    if (lane < 4) {
        float dv = g_dinv[gw];
        float4 l = make_float4(-1e30f, -1e30f, -1e30f, -1e30f);
        if (q < 3) {
            float4 g = *(const float4*)(g_g2 + (size_t)gw * CP + q * 4);
            l.x = fmaf(dv, acc.x + g.x, b2s[q * 4 + 0]);
            l.y = fmaf(dv, acc.y + g.y, b2s[q * 4 + 1]);
            if (q < 2) {
                l.z = fmaf(dv, acc.z + g.z, b2s[q * 4 + 2]);
                l.w = fmaf(dv, acc.w + g.w, b2s[q * 4 + 3]);
            }
        }
        float mx = fmaxf(fmaxf(l.x, l.y), fmaxf(l.z, l.w));
#pragma unroll
        for (int st = 1; st < 4; st <<= 1)
            mx = fmaxf(mx, __shfl_xor_sync(0xF, mx, st));

        float4 ev;
        ev.x = (l.x > -1e29f) ? expf(l.x - mx) : 0.f;
        ev.y = (l.y > -1e29f) ? expf(l.y - mx) : 0.f;
        ev.z = (l.z > -1e29f) ? expf(l.z - mx) : 0.f;
        ev.w = (l.w > -1e29f) ? expf(l.w - mx) : 0.f;
        float s = ev.x + ev.y + ev.z + ev.w;
#pragma unroll
        for (int st = 1; st < 4; st <<= 1)
            s += __shfl_xor_sync(0xF, s, st);
        float inv = 1.0f / s;

        if (q < 3) {
            float* o = outp + (size_t)gw * NC + q * 4;
            o[0] = ev.x * inv;
            o[1] = ev.y * inv;
            if (q < 2) { o[2] = ev.z * inv; o[3] = ev.w * inv; }
        }
    }
}

// ---------------------------------------------------------------
extern "C" void kernel_launch(void* const* d_in, const int* in_sizes, int n_in,
                              void* d_out, int out_size) {
    const float* x  = (const float*)d_in[0];
    const int*   ei = (const int*)  d_in[1];
    const float* W1 = (const float*)d_in[2];
    const float* b1 = (const float*)d_in[3];
    const float* W2 = (const float*)d_in[4];
    const float* b2 = (const float*)d_in[5];
    float* out = (float*)d_out;

    int n = in_sizes[0] / F_IN;
    int e = in_sizes[1] / 2;
    const int* src = ei;
    const int* dst = ei + e;
    int nb = (n + 255) / 256;   // <=512 (g_bsum capacity)

    zero_kernel <<<nb, 256>>>(n);
    deg_kernel  <<<(e + 255) / 256, 256>>>(dst, e);
    scan1_kernel<<<nb, 256>>>(n);
    scan3_kernel<<<nb, 256>>>(n);
    place_kernel<<<(e + 255) / 256, 256>>>(src, dst, e);
    gemm1_kernel<<<nb, 256>>>(x, W1, n);
    gf1_kernel  <<<(n * 32 + 255) / 256, 256>>>(b1, W2, n);
    gf2_kernel  <<<(n * 32 + 255) / 256, 256>>>(b2, out, n);
}

// round 13
// speedup vs baseline: 1.1335x; 1.1335x over previous
#include <cuda_runtime.h>
#include <math.h>

#define NMAX 100000
#define EMAX 3200000
#define F_IN 128
#define HID  16
#define NC   10
#define CP   12   // layer-2 row stride: 12 floats = 48B, float4-aligned

// ---- scratch (static device globals; no allocation allowed) ----
__device__ float g_g1  [NMAX * HID];  // (x@W1) * dinv[src-side]
__device__ float g_tmp1[NMAX * HID];  // gathered sums layer 1
__device__ float g_g2  [NMAX * CP];   // (h@W2) * dinv, padded to 12
__device__ float g_tmp2[NMAX * CP];   // gathered sums layer 2
__device__ float g_dinv[NMAX];
__device__ int   g_cnt [NMAX];        // in-degree (dst counts)
__device__ int   g_cnt2[NMAX];        // placement cursors (init = base)
__device__ int   g_base[NMAX];        // CSR row offsets (by dst)
__device__ int   g_bsum[512];         // block sums for scan
__device__ int   g_csr [EMAX];        // src indices grouped by dst

// ---------------------------------------------------------------
__global__ void zero_kernel(int n) {
    int i = blockIdx.x * blockDim.x + threadIdx.x;
    if (i < n) g_cnt[i] = 0;
}

// ---- deg: vectorized int4 index read (4 edges/thread) + scalar tail ----
__global__ void deg_kernel_v(const int* __restrict__ dst, int e) {
    int t = blockIdx.x * blockDim.x + threadIdx.x;
    int vecn = e >> 2;
    if (t < vecn) {
        int4 d4 = ((const int4*)dst)[t];
        atomicAdd(&g_cnt[d4.x], 1);
        atomicAdd(&g_cnt[d4.y], 1);
        atomicAdd(&g_cnt[d4.z], 1);
        atomicAdd(&g_cnt[d4.w], 1);
    } else {
        int i = (vecn << 2) + (t - vecn);
        if (i < e) atomicAdd(&g_cnt[dst[i]], 1);
    }
}
__global__ void deg_kernel_s(const int* __restrict__ dst, int e) {
    int i = blockIdx.x * blockDim.x + threadIdx.x;
    if (i < e) atomicAdd(&g_cnt[dst[i]], 1);
}

// ---- scan stage 1 (+ fused dinv): per-block sums of g_cnt ----
__global__ __launch_bounds__(256) void scan1_kernel(int n) {
    __shared__ int wsum[8];
    int i = blockIdx.x * 256 + threadIdx.x;
    int lane = threadIdx.x & 31, warp = threadIdx.x >> 5;
    int v = (i < n) ? g_cnt[i] : 0;
    if (i < n) g_dinv[i] = rsqrtf((float)v + 1.0f);
    int s = v;
#pragma unroll
    for (int d = 16; d > 0; d >>= 1) s += __shfl_down_sync(~0u, s, d);
    if (lane == 0) wsum[warp] = s;
    __syncthreads();
    if (threadIdx.x == 0) {
        int t = 0;
#pragma unroll
        for (int w = 0; w < 8; ++w) t += wsum[w];
        g_bsum[blockIdx.x] = t;
    }
}

// ---- scan stage 2+3 fused -> g_base (and cursor g_cnt2 = base) ----
__global__ __launch_bounds__(256) void scan3_kernel(int n) {
    __shared__ int wsum[8];
    __shared__ int wred[8];
    __shared__ int s_boff;
    int lane = threadIdx.x & 31, warp = threadIdx.x >> 5;

    int partial = 0;
    for (int j = threadIdx.x; j < blockIdx.x; j += 256) partial += g_bsum[j];
#pragma unroll
    for (int d = 16; d > 0; d >>= 1) partial += __shfl_down_sync(~0u, partial, d);
    if (lane == 0) wred[warp] = partial;
    __syncthreads();
    if (threadIdx.x == 0) {
        int t = 0;
#pragma unroll
        for (int w = 0; w < 8; ++w) t += wred[w];
        s_boff = t;
    }

    int i = blockIdx.x * 256 + threadIdx.x;
    int orig = (i < n) ? g_cnt[i] : 0;
    int v = orig;
#pragma unroll
    for (int d = 1; d < 32; d <<= 1) {
        int t = __shfl_up_sync(~0u, v, d);
        if (lane >= d) v += t;
    }
    if (lane == 31) wsum[warp] = v;
    __syncthreads();
    if (warp == 0 && lane < 8) {
        int s = wsum[lane];
#pragma unroll
        for (int d = 1; d < 8; d <<= 1) {
            int t = __shfl_up_sync(0xffu, s, d);
            if (lane >= d) s += t;
        }
        wsum[lane] = s;
    }
    __syncthreads();
    int wbase = (warp > 0) ? wsum[warp - 1] : 0;
    if (i < n) {
        int base = s_boff + wbase + v - orig;
        g_base[i] = base;
        g_cnt2[i] = base;     // cursor starts at base
    }
}

// ---- CSR placement: cursor atomic gives the slot directly ----
__global__ void place_kernel_v(const int* __restrict__ src,
                               const int* __restrict__ dst, int e) {
    int t = blockIdx.x * blockDim.x + threadIdx.x;
    int vecn = e >> 2;
    if (t < vecn) {
        int4 s4 = ((const int4*)src)[t];
        int4 d4 = ((const int4*)dst)[t];
        g_csr[atomicAdd(&g_cnt2[d4.x], 1)] = s4.x;
        g_csr[atomicAdd(&g_cnt2[d4.y], 1)] = s4.y;
        g_csr[atomicAdd(&g_cnt2[d4.z], 1)] = s4.z;
        g_csr[atomicAdd(&g_cnt2[d4.w], 1)] = s4.w;
    } else {
        int i = (vecn << 2) + (t - vecn);
        if (i < e) g_csr[atomicAdd(&g_cnt2[dst[i]], 1)] = src[i];
    }
}
__global__ void place_kernel_s(const int* __restrict__ src,
                               const int* __restrict__ dst, int e) {
    int i = blockIdx.x * blockDim.x + threadIdx.x;
    if (i < e) g_csr[atomicAdd(&g_cnt2[dst[i]], 1)] = src[i];
}

// ---- GEMM1: g1 = (x @ W1) * dinv (warp-staged; measured-good) ----
__global__ __launch_bounds__(256) void gemm1_kernel(const float* __restrict__ x,
                                                    const float* __restrict__ W1,
                                                    int n) {
    __shared__ float w1s[F_IN * HID];
    __shared__ float xs[8][32][33];
#pragma unroll
    for (int i = threadIdx.x; i < F_IN * HID; i += 256)
        w1s[i] = W1[i];
    __syncthreads();

    const int warp = threadIdx.x >> 5;
    const int lane = threadIdx.x & 31;
    const int row0 = blockIdx.x * 256 + warp * 32;
    const int myrow = row0 + lane;

    float acc[16];
#pragma unroll
    for (int o = 0; o < 16; ++o) acc[o] = 0.f;

#pragma unroll 1
    for (int kc = 0; kc < 4; ++kc) {
#pragma unroll 8
        for (int r = 0; r < 32; ++r) {
            int row = row0 + r;
            xs[warp][r][lane] = (row < n)
                ? x[(size_t)row * F_IN + kc * 32 + lane] : 0.f;
        }
        __syncwarp();
#pragma unroll
        for (int k = 0; k < 32; ++k) {
            float xv = xs[warp][lane][k];
            const float* w = w1s + (kc * 32 + k) * HID;
            float4 wa = *(const float4*)(w + 0);
            float4 wb = *(const float4*)(w + 4);
            float4 wc = *(const float4*)(w + 8);
            float4 wd = *(const float4*)(w + 12);
            acc[0]  = fmaf(xv, wa.x, acc[0]);  acc[1]  = fmaf(xv, wa.y, acc[1]);
            acc[2]  = fmaf(xv, wa.z, acc[2]);  acc[3]  = fmaf(xv, wa.w, acc[3]);
            acc[4]  = fmaf(xv, wb.x, acc[4]);  acc[5]  = fmaf(xv, wb.y, acc[5]);
            acc[6]  = fmaf(xv, wb.z, acc[6]);  acc[7]  = fmaf(xv, wb.w, acc[7]);
            acc[8]  = fmaf(xv, wc.x, acc[8]);  acc[9]  = fmaf(xv, wc.y, acc[9]);
            acc[10] = fmaf(xv, wc.z, acc[10]); acc[11] = fmaf(xv, wc.w, acc[11]);
            acc[12] = fmaf(xv, wd.x, acc[12]); acc[13] = fmaf(xv, wd.y, acc[13]);
            acc[14] = fmaf(xv, wd.z, acc[14]); acc[15] = fmaf(xv, wd.w, acc[15]);
        }
        __syncwarp();
    }

    if (myrow < n) {
        float dv = g_dinv[myrow];
        float* out = g_g1 + (size_t)myrow * HID;
#pragma unroll
        for (int o = 0; o < 16; o += 4)
            *(float4*)(out + o) = make_float4(acc[o] * dv, acc[o + 1] * dv,
                                              acc[o + 2] * dv, acc[o + 3] * dv);
    }
}

// ---- gather: warp per node, 4-lane edge groups, butterfly reduce.
// LAYER 0: stride 16, 4 quarters. LAYER 1: stride 12, 3 quarters. ----
template <int LAYER>
__global__ __launch_bounds__(256) void gather_kernel(int n) {
    const float* __restrict__ in = (LAYER == 0) ? g_g1 : g_g2;
    float* __restrict__ out      = (LAYER == 0) ? g_tmp1 : g_tmp2;
    const int stride = (LAYER == 0) ? HID : CP;
    const int nq     = (LAYER == 0) ? 4 : 3;

    int gw = (blockIdx.x * 256 + threadIdx.x) >> 5;
    if (gw >= n) return;
    int lane = threadIdx.x & 31;
    int eq = lane >> 2, q = lane & 3;
    int start = g_base[gw];
    int m = g_cnt[gw];
    const int* cs = g_csr + start;

    float4 acc = make_float4(0.f, 0.f, 0.f, 0.f);
    if (q < nq) {
        int j = eq;
        for (; j + 8 < m; j += 16) {
            int s0 = cs[j], s1 = cs[j + 8];
            float4 a = *(const float4*)(in + (size_t)s0 * stride + q * 4);
            float4 b = *(const float4*)(in + (size_t)s1 * stride + q * 4);
            acc.x += a.x + b.x; acc.y += a.y + b.y;
            acc.z += a.z + b.z; acc.w += a.w + b.w;
        }
        for (; j < m; j += 8) {
            int s = cs[j];
            float4 a = *(const float4*)(in + (size_t)s * stride + q * 4);
            acc.x += a.x; acc.y += a.y; acc.z += a.z; acc.w += a.w;
        }
    }
#pragma unroll
    for (int st = 4; st < 32; st <<= 1) {
        acc.x += __shfl_xor_sync(~0u, acc.x, st);
        acc.y += __shfl_xor_sync(~0u, acc.y, st);
        acc.z += __shfl_xor_sync(~0u, acc.z, st);
        acc.w += __shfl_xor_sync(~0u, acc.w, st);
    }
    if (lane < nq)
        *(float4*)(out + (size_t)gw * stride + q * 4) = acc;
}

// ---- finalize layer1 + GEMM2: h=relu(dinv*(tmp1+g1)+b1); g2=(h@W2)*dinv ----
__global__ __launch_bounds__(256) void fin1_kernel(const float* __restrict__ b1,
                                                   const float* __restrict__ W2,
                                                   int n) {
    __shared__ float w2s[HID * NC];
    __shared__ float b1s[HID];
    int tid = threadIdx.x;
    if (tid < HID * NC) w2s[tid] = W2[tid];
    if (tid < HID)      b1s[tid] = b1[tid];
    __syncthreads();

    int i = blockIdx.x * 256 + tid;
    if (i >= n) return;
    float dv = g_dinv[i];

    float h[16];
    const float4* tp = (const float4*)(g_tmp1 + (size_t)i * HID);
    const float4* gp = (const float4*)(g_g1 + (size_t)i * HID);
#pragma unroll
    for (int o4 = 0; o4 < 4; ++o4) {
        float4 t = tp[o4], g = gp[o4];
        h[o4 * 4 + 0] = fmaxf(fmaf(dv, t.x + g.x, b1s[o4 * 4 + 0]), 0.f);
        h[o4 * 4 + 1] = fmaxf(fmaf(dv, t.y + g.y, b1s[o4 * 4 + 1]), 0.f);
        h[o4 * 4 + 2] = fmaxf(fmaf(dv, t.z + g.z, b1s[o4 * 4 + 2]), 0.f);
        h[o4 * 4 + 3] = fmaxf(fmaf(dv, t.w + g.w, b1s[o4 * 4 + 3]), 0.f);
    }

    float acc[NC];
#pragma unroll
    for (int c = 0; c < NC; ++c) acc[c] = 0.f;
#pragma unroll
    for (int o = 0; o < HID; ++o) {
        float hv = h[o];
#pragma unroll
        for (int c = 0; c < NC; ++c) acc[c] = fmaf(hv, w2s[o * NC + c], acc[c]);
    }

    float* out = g_g2 + (size_t)i * CP;
    ((float4*)out)[0] = make_float4(acc[0] * dv, acc[1] * dv, acc[2] * dv, acc[3] * dv);
    ((float4*)out)[1] = make_float4(acc[4] * dv, acc[5] * dv, acc[6] * dv, acc[7] * dv);
    ((float4*)out)[2] = make_float4(acc[8] * dv, acc[9] * dv, 0.f, 0.f);
}

// ---- finalize layer2 + softmax ----
__global__ __launch_bounds__(256) void fin2_kernel(const float* __restrict__ b2,
                                                   float* __restrict__ out, int n) {
    __shared__ float b2s[NC];
    if (threadIdx.x < NC) b2s[threadIdx.x] = b2[threadIdx.x];
    __syncthreads();
    int i = blockIdx.x * blockDim.x + threadIdx.x;
    if (i >= n) return;
    float dv = g_dinv[i];
    const float* tp = g_tmp2 + (size_t)i * CP;
    const float* gp = g_g2 + (size_t)i * CP;
    float l[NC];
    float m = -1e30f;
#pragma unroll
    for (int c = 0; c < NC; ++c) {
        l[c] = fmaf(dv, tp[c] + gp[c], b2s[c]);
        m = fmaxf(m, l[c]);
    }
    float sum = 0.f;
#pragma unroll
    for (int c = 0; c < NC; ++c) {
        l[c] = expf(l[c] - m);
        sum += l[c];
    }
    float inv = 1.0f / sum;
#pragma unroll
    for (int c = 0; c < NC; ++c) out[i * NC + c] = l[c] * inv;
}

// ---------------------------------------------------------------
extern "C" void kernel_launch(void* const* d_in, const int* in_sizes, int n_in,
                              void* d_out, int out_size) {
    const float* x  = (const float*)d_in[0];
    const int*   ei = (const int*)  d_in[1];
    const float* W1 = (const float*)d_in[2];
    const float* b1 = (const float*)d_in[3];
    const float* W2 = (const float*)d_in[4];
    const float* b2 = (const float*)d_in[5];
    float* out = (float*)d_out;

    int n = in_sizes[0] / F_IN;
    int e = in_sizes[1] / 2;
    const int* src = ei;
    const int* dst = ei + e;
    int nb = (n + 255) / 256;   // <=512 (g_bsum capacity)

    // int4 paths require src/dst 16B-aligned (true when e % 4 == 0)
    bool aligned = ((e & 3) == 0) &&
                   ((((size_t)src) & 15) == 0) && ((((size_t)dst) & 15) == 0);

    zero_kernel <<<nb, 256>>>(n);
    if (aligned) {
        int t = (e >> 2);
        deg_kernel_v<<<(t + 255) / 256, 256>>>(dst, e);
    } else {
        deg_kernel_s<<<(e + 255) / 256, 256>>>(dst, e);
    }
    scan1_kernel<<<nb, 256>>>(n);
    scan3_kernel<<<nb, 256>>>(n);
    if (aligned) {
        int t = (e >> 2);
        place_kernel_v<<<(t + 255) / 256, 256>>>(src, dst, e);
    } else {
        place_kernel_s<<<(e + 255) / 256, 256>>>(src, dst, e);
    }
    gemm1_kernel<<<nb, 256>>>(x, W1, n);
    gather_kernel<0><<<(n * 32 + 255) / 256, 256>>>(n);
    fin1_kernel <<<nb, 256>>>(b1, W2, n);
    gather_kernel<1><<<(n * 32 + 255) / 256, 256>>>(n);
    fin2_kernel <<<nb, 256>>>(b2, out, n);
}

// round 14
// speedup vs baseline: 1.1813x; 1.0422x over previous
#include <cuda_runtime.h>
#include <cuda_fp16.h>
#include <math.h>

#define NMAX 100000
#define EMAX 3200000
#define F_IN 128
#define HID  16
#define NC   10
#define CPH  12   // layer-2 halfs per row: 10 + 2 pad = 24B, 8B-aligned rows

// ---- scratch (static device globals; no allocation allowed) ----
__device__ __align__(16) __half g_g1h[NMAX * HID];  // (x@W1)*dinv, fp16
__device__ __align__(16) __half g_g2h[NMAX * CPH];  // (h@W2)*dinv, fp16
__device__ float g_tmp1[NMAX * HID];  // gathered sums layer 1 (fp32)
__device__ float g_tmp2[NMAX * CPH]; // gathered sums layer 2 (fp32)
__device__ float g_dinv[NMAX];
__device__ int   g_cnt [NMAX];
__device__ int   g_cnt2[NMAX];        // placement cursors (init = base)
__device__ int   g_base[NMAX];
__device__ int   g_bsum[512];
__device__ int   g_csr [EMAX];

// ---------------------------------------------------------------
__global__ void zero_kernel(int n) {
    int i = blockIdx.x * blockDim.x + threadIdx.x;
    if (i < n) g_cnt[i] = 0;
}

__global__ void deg_kernel_v(const int* __restrict__ dst, int e) {
    int t = blockIdx.x * blockDim.x + threadIdx.x;
    int vecn = e >> 2;
    if (t < vecn) {
        int4 d4 = ((const int4*)dst)[t];
        atomicAdd(&g_cnt[d4.x], 1);
        atomicAdd(&g_cnt[d4.y], 1);
        atomicAdd(&g_cnt[d4.z], 1);
        atomicAdd(&g_cnt[d4.w], 1);
    } else {
        int i = (vecn << 2) + (t - vecn);
        if (i < e) atomicAdd(&g_cnt[dst[i]], 1);
    }
}
__global__ void deg_kernel_s(const int* __restrict__ dst, int e) {
    int i = blockIdx.x * blockDim.x + threadIdx.x;
    if (i < e) atomicAdd(&g_cnt[dst[i]], 1);
}

// ---- scan stage 1 (+ fused dinv) ----
__global__ __launch_bounds__(256) void scan1_kernel(int n) {
    __shared__ int wsum[8];
    int i = blockIdx.x * 256 + threadIdx.x;
    int lane = threadIdx.x & 31, warp = threadIdx.x >> 5;
    int v = (i < n) ? g_cnt[i] : 0;
    if (i < n) g_dinv[i] = rsqrtf((float)v + 1.0f);
    int s = v;
#pragma unroll
    for (int d = 16; d > 0; d >>= 1) s += __shfl_down_sync(~0u, s, d);
    if (lane == 0) wsum[warp] = s;
    __syncthreads();
    if (threadIdx.x == 0) {
        int t = 0;
#pragma unroll
        for (int w = 0; w < 8; ++w) t += wsum[w];
        g_bsum[blockIdx.x] = t;
    }
}

// ---- scan stage 2+3 fused -> g_base, cursor ----
__global__ __launch_bounds__(256) void scan3_kernel(int n) {
    __shared__ int wsum[8];
    __shared__ int wred[8];
    __shared__ int s_boff;
    int lane = threadIdx.x & 31, warp = threadIdx.x >> 5;

    int partial = 0;
    for (int j = threadIdx.x; j < blockIdx.x; j += 256) partial += g_bsum[j];
#pragma unroll
    for (int d = 16; d > 0; d >>= 1) partial += __shfl_down_sync(~0u, partial, d);
    if (lane == 0) wred[warp] = partial;
    __syncthreads();
    if (threadIdx.x == 0) {
        int t = 0;
#pragma unroll
        for (int w = 0; w < 8; ++w) t += wred[w];
        s_boff = t;
    }

    int i = blockIdx.x * 256 + threadIdx.x;
    int orig = (i < n) ? g_cnt[i] : 0;
    int v = orig;
#pragma unroll
    for (int d = 1; d < 32; d <<= 1) {
        int t = __shfl_up_sync(~0u, v, d);
        if (lane >= d) v += t;
    }
    if (lane == 31) wsum[warp] = v;
    __syncthreads();
    if (warp == 0 && lane < 8) {
        int s = wsum[lane];
#pragma unroll
        for (int d = 1; d < 8; d <<= 1) {
            int t = __shfl_up_sync(0xffu, s, d);
            if (lane >= d) s += t;
        }
        wsum[lane] = s;
    }
    __syncthreads();
    int wbase = (warp > 0) ? wsum[warp - 1] : 0;
    if (i < n) {
        int base = s_boff + wbase + v - orig;
        g_base[i] = base;
        g_cnt2[i] = base;
    }
}

// ---- CSR placement ----
__global__ void place_kernel_v(const int* __restrict__ src,
                               const int* __restrict__ dst, int e) {
    int t = blockIdx.x * blockDim.x + threadIdx.x;
    int vecn = e >> 2;
    if (t < vecn) {
        int4 s4 = ((const int4*)src)[t];
        int4 d4 = ((const int4*)dst)[t];
        g_csr[atomicAdd(&g_cnt2[d4.x], 1)] = s4.x;
        g_csr[atomicAdd(&g_cnt2[d4.y], 1)] = s4.y;
        g_csr[atomicAdd(&g_cnt2[d4.z], 1)] = s4.z;
        g_csr[atomicAdd(&g_cnt2[d4.w], 1)] = s4.w;
    } else {
        int i = (vecn << 2) + (t - vecn);
        if (i < e) g_csr[atomicAdd(&g_cnt2[dst[i]], 1)] = src[i];
    }
}
__global__ void place_kernel_s(const int* __restrict__ src,
                               const int* __restrict__ dst, int e) {
    int i = blockIdx.x * blockDim.x + threadIdx.x;
    if (i < e) g_csr[atomicAdd(&g_cnt2[dst[i]], 1)] = src[i];
}

// ---- GEMM1: g1h = fp16((x @ W1) * dinv) (warp-staged) ----
__global__ __launch_bounds__(256) void gemm1_kernel(const float* __restrict__ x,
                                                    const float* __restrict__ W1,
                                                    int n) {
    __shared__ float w1s[F_IN * HID];
    __shared__ float xs[8][32][33];
#pragma unroll
    for (int i = threadIdx.x; i < F_IN * HID; i += 256)
        w1s[i] = W1[i];
    __syncthreads();

    const int warp = threadIdx.x >> 5;
    const int lane = threadIdx.x & 31;
    const int row0 = blockIdx.x * 256 + warp * 32;
    const int myrow = row0 + lane;

    float acc[16];
#pragma unroll
    for (int o = 0; o < 16; ++o) acc[o] = 0.f;

#pragma unroll 1
    for (int kc = 0; kc < 4; ++kc) {
#pragma unroll 8
        for (int r = 0; r < 32; ++r) {
            int row = row0 + r;
            xs[warp][r][lane] = (row < n)
                ? x[(size_t)row * F_IN + kc * 32 + lane] : 0.f;
        }
        __syncwarp();
#pragma unroll
        for (int k = 0; k < 32; ++k) {
            float xv = xs[warp][lane][k];
            const float* w = w1s + (kc * 32 + k) * HID;
            float4 wa = *(const float4*)(w + 0);
            float4 wb = *(const float4*)(w + 4);
            float4 wc = *(const float4*)(w + 8);
            float4 wd = *(const float4*)(w + 12);
            acc[0]  = fmaf(xv, wa.x, acc[0]);  acc[1]  = fmaf(xv, wa.y, acc[1]);
            acc[2]  = fmaf(xv, wa.z, acc[2]);  acc[3]  = fmaf(xv, wa.w, acc[3]);
            acc[4]  = fmaf(xv, wb.x, acc[4]);  acc[5]  = fmaf(xv, wb.y, acc[5]);
            acc[6]  = fmaf(xv, wb.z, acc[6]);  acc[7]  = fmaf(xv, wb.w, acc[7]);
            acc[8]  = fmaf(xv, wc.x, acc[8]);  acc[9]  = fmaf(xv, wc.y, acc[9]);
            acc[10] = fmaf(xv, wc.z, acc[10]); acc[11] = fmaf(xv, wc.w, acc[11]);
            acc[12] = fmaf(xv, wd.x, acc[12]); acc[13] = fmaf(xv, wd.y, acc[13]);
            acc[14] = fmaf(xv, wd.z, acc[14]); acc[15] = fmaf(xv, wd.w, acc[15]);
        }
        __syncwarp();
    }

    if (myrow < n) {
        float dv = g_dinv[myrow];
        __half2 h[8];
#pragma unroll
        for (int o = 0; o < 8; ++o)
            h[o] = __floats2half2_rn(acc[o * 2] * dv, acc[o * 2 + 1] * dv);
        uint4* out = (uint4*)(g_g1h + (size_t)myrow * HID);
        out[0] = *(uint4*)&h[0];
        out[1] = *(uint4*)&h[4];
    }
}

// ---- gather: warp per node, 4-lane edge groups over fp16 rows,
// fp32 accumulate, butterfly reduce, fp32 tmp write.
// LAYER 0: 16 halfs (32B) rows, 4 quarters. LAYER 1: 12 halfs (24B), 3 q. ----
template <int LAYER>
__global__ __launch_bounds__(256) void gather_kernel(int n) {
    const __half* __restrict__ in = (LAYER == 0) ? g_g1h : g_g2h;
    float* __restrict__ out       = (LAYER == 0) ? g_tmp1 : g_tmp2;
    const int stride = (LAYER == 0) ? HID : CPH;  // halfs per row
    const int nq     = (LAYER == 0) ? 4 : 3;

    int gw = (blockIdx.x * 256 + threadIdx.x) >> 5;
    if (gw >= n) return;
    int lane = threadIdx.x & 31;
    int eq = lane >> 2, q = lane & 3;
    int m = g_cnt[gw];
    const int* cs = g_csr + g_base[gw];

    float4 acc = make_float4(0.f, 0.f, 0.f, 0.f);
    if (q < nq) {
        int j = eq;
        for (; j + 8 < m; j += 16) {
            int s0 = cs[j], s1 = cs[j + 8];
            uint2 va = *(const uint2*)(in + (size_t)s0 * stride + q * 4);
            uint2 vb = *(const uint2*)(in + (size_t)s1 * stride + q * 4);
            float2 a0 = __half22float2(*(const __half2*)&va.x);
            float2 a1 = __half22float2(*(const __half2*)&va.y);
            float2 b0 = __half22float2(*(const __half2*)&vb.x);
            float2 b1 = __half22float2(*(const __half2*)&vb.y);
            acc.x += a0.x + b0.x; acc.y += a0.y + b0.y;
            acc.z += a1.x + b1.x; acc.w += a1.y + b1.y;
        }
        for (; j < m; j += 8) {
            int s = cs[j];
            uint2 va = *(const uint2*)(in + (size_t)s * stride + q * 4);
            float2 a0 = __half22float2(*(const __half2*)&va.x);
            float2 a1 = __half22float2(*(const __half2*)&va.y);
            acc.x += a0.x; acc.y += a0.y;
            acc.z += a1.x; acc.w += a1.y;
        }
    }
#pragma unroll
    for (int st = 4; st < 32; st <<= 1) {
        acc.x += __shfl_xor_sync(~0u, acc.x, st);
        acc.y += __shfl_xor_sync(~0u, acc.y, st);
        acc.z += __shfl_xor_sync(~0u, acc.z, st);
        acc.w += __shfl_xor_sync(~0u, acc.w, st);
    }
    if (lane < nq)
        *(float4*)(out + (size_t)gw * stride + q * 4) = acc;
}

// ---- finalize layer1 + GEMM2: h=relu(dinv*(tmp1+g1)+b1); g2h=fp16((h@W2)*dinv) ----
__global__ __launch_bounds__(256) void fin1_kernel(const float* __restrict__ b1,
                                                   const float* __restrict__ W2,
                                                   int n) {
    __shared__ float w2s[HID * NC];
    __shared__ float b1s[HID];
    int tid = threadIdx.x;
    if (tid < HID * NC) w2s[tid] = W2[tid];
    if (tid < HID)      b1s[tid] = b1[tid];
    __syncthreads();

    int i = blockIdx.x * 256 + tid;
    if (i >= n) return;
    float dv = g_dinv[i];

    float h[16];
    const float4* tp = (const float4*)(g_tmp1 + (size_t)i * HID);
    const __half2* gp = (const __half2*)(g_g1h + (size_t)i * HID);
#pragma unroll
    for (int o4 = 0; o4 < 4; ++o4) {
        float4 t = tp[o4];
        float2 ga = __half22float2(gp[o4 * 2]);
        float2 gb = __half22float2(gp[o4 * 2 + 1]);
        h[o4 * 4 + 0] = fmaxf(fmaf(dv, t.x + ga.x, b1s[o4 * 4 + 0]), 0.f);
        h[o4 * 4 + 1] = fmaxf(fmaf(dv, t.y + ga.y, b1s[o4 * 4 + 1]), 0.f);
        h[o4 * 4 + 2] = fmaxf(fmaf(dv, t.z + gb.x, b1s[o4 * 4 + 2]), 0.f);
        h[o4 * 4 + 3] = fmaxf(fmaf(dv, t.w + gb.y, b1s[o4 * 4 + 3]), 0.f);
    }

    float acc[NC];
#pragma unroll
    for (int c = 0; c < NC; ++c) acc[c] = 0.f;
#pragma unroll
    for (int o = 0; o < HID; ++o) {
        float hv = h[o];
#pragma unroll
        for (int c = 0; c < NC; ++c) acc[c] = fmaf(hv, w2s[o * NC + c], acc[c]);
    }

    __half2 p[6];
#pragma unroll
    for (int c = 0; c < 5; ++c)
        p[c] = __floats2half2_rn(acc[c * 2] * dv, acc[c * 2 + 1] * dv);
    p[5] = __floats2half2_rn(0.f, 0.f);
    uint2* out = (uint2*)(g_g2h + (size_t)i * CPH);
    out[0] = *(uint2*)&p[0];
    out[1] = *(uint2*)&p[2];
    out[2] = *(uint2*)&p[4];
}

// ---- finalize layer2 + softmax ----
__global__ __launch_bounds__(256) void fin2_kernel(const float* __restrict__ b2,
                                                   float* __restrict__ out, int n) {
    __shared__ float b2s[NC];
    if (threadIdx.x < NC) b2s[threadIdx.x] = b2[threadIdx.x];
    __syncthreads();
    int i = blockIdx.x * blockDim.x + threadIdx.x;
    if (i >= n) return;
    float dv = g_dinv[i];
    const float* tp = g_tmp2 + (size_t)i * CPH;
    const __half2* gp = (const __half2*)(g_g2h + (size_t)i * CPH);
    float g[10];
#pragma unroll
    for (int c = 0; c < 5; ++c) {
        float2 f = __half22float2(gp[c]);
        g[c * 2] = f.x; g[c * 2 + 1] = f.y;
    }
    float l[NC];
    float m = -1e30f;
#pragma unroll
    for (int c = 0; c < NC; ++c) {
        l[c] = fmaf(dv, tp[c] + g[c], b2s[c]);
        m = fmaxf(m, l[c]);
    }
    float sum = 0.f;
#pragma unroll
    for (int c = 0; c < NC; ++c) {
        l[c] = expf(l[c] - m);
        sum += l[c];
    }
    float inv = 1.0f / sum;
#pragma unroll
    for (int c = 0; c < NC; ++c) out[i * NC + c] = l[c] * inv;
}

// ---------------------------------------------------------------
extern "C" void kernel_launch(void* const* d_in, const int* in_sizes, int n_in,
                              void* d_out, int out_size) {
    const float* x  = (const float*)d_in[0];
    const int*   ei = (const int*)  d_in[1];
    const float* W1 = (const float*)d_in[2];
    const float* b1 = (const float*)d_in[3];
    const float* W2 = (const float*)d_in[4];
    const float* b2 = (const float*)d_in[5];
    float* out = (float*)d_out;

    int n = in_sizes[0] / F_IN;
    int e = in_sizes[1] / 2;
    const int* src = ei;
    const int* dst = ei + e;
    int nb = (n + 255) / 256;

    bool aligned = ((e & 3) == 0) &&
                   ((((size_t)src) & 15) == 0) && ((((size_t)dst) & 15) == 0);

    zero_kernel <<<nb, 256>>>(n);
    if (aligned) {
        int t = (e >> 2);
        deg_kernel_v<<<(t + 255) / 256, 256>>>(dst, e);
    } else {
        deg_kernel_s<<<(e + 255) / 256, 256>>>(dst, e);
    }
    scan1_kernel<<<nb, 256>>>(n);
    scan3_kernel<<<nb, 256>>>(n);
    if (aligned) {
        int t = (e >> 2);
        place_kernel_v<<<(t + 255) / 256, 256>>>(src, dst, e);
    } else {
        place_kernel_s<<<(e + 255) / 256, 256>>>(src, dst, e);
    }
    gemm1_kernel<<<nb, 256>>>(x, W1, n);
    gather_kernel<0><<<(n * 32 + 255) / 256, 256>>>(n);
    fin1_kernel <<<nb, 256>>>(b1, W2, n);
    gather_kernel<1><<<(n * 32 + 255) / 256, 256>>>(n);
    fin2_kernel <<<nb, 256>>>(b2, out, n);
}